// round 6
// baseline (speedup 1.0000x reference)
#include <cuda_runtime.h>
#include <math.h>

#define CH 28
#define INV_SQ8 0.35355339059327373f
#define NMAX 1050000

// Scratch (allocation-free contract: __device__ globals)
__device__ float  g_vol1[CH * 32 * 32 * 32];             //  3.5 MB fp32
__device__ float  g_vol2[CH * 64 * 64 * 64];             //   28 MB fp32
__device__ float  g_volF[(size_t)128 * 128 * 128 * CH];  //  235 MB fp32, (z,y,x,c) tight
__device__ float4 g_sorted[NMAX];                        // z-bucket-sorted (x,y,z,idx)
__device__ int    g_hist[128];
__device__ int    g_cursor[128];

// ---------------------------------------------------------------------------
// Sorting chain: bucket points by z0 (127 bins) with a counting sort so the
// query kernel walks the volume in z order -> 2-plane (3.7 MB) L2 working set.
// ---------------------------------------------------------------------------
__device__ __forceinline__ int zbin(float z) {
    float pz = (z / 1.5f + 1.0f) * 63.5f;
    return min(max((int)floorf(pz), 0), 126);
}

__global__ void zero_hist_kernel() {
    if (threadIdx.x < 128) g_hist[threadIdx.x] = 0;
}

__global__ void hist_kernel(const float* __restrict__ xyz, int N) {
    __shared__ int sh[128];
    if (threadIdx.x < 128) sh[threadIdx.x] = 0;
    __syncthreads();
    for (int i = blockIdx.x * blockDim.x + threadIdx.x; i < N;
         i += gridDim.x * blockDim.x)
        atomicAdd(&sh[zbin(xyz[3 * i + 2])], 1);
    __syncthreads();
    if (threadIdx.x < 128 && sh[threadIdx.x])
        atomicAdd(&g_hist[threadIdx.x], sh[threadIdx.x]);
}

__global__ void scan_kernel() {
    __shared__ int s[128];
    int t = threadIdx.x;            // blockDim = 128
    int v = g_hist[t];
    s[t] = v;
    __syncthreads();
#pragma unroll
    for (int off = 1; off < 128; off <<= 1) {
        int u = (t >= off) ? s[t - off] : 0;
        __syncthreads();
        s[t] += u;
        __syncthreads();
    }
    g_cursor[t] = s[t] - v;         // exclusive prefix
}

__global__ void scatter_kernel(const float* __restrict__ xyz, int N) {
    for (int i = blockIdx.x * blockDim.x + threadIdx.x; i < N;
         i += gridDim.x * blockDim.x) {
        float x = xyz[3 * i + 0];
        float y = xyz[3 * i + 1];
        float z = xyz[3 * i + 2];
        int pos = atomicAdd(&g_cursor[zbin(z)], 1);
        g_sorted[pos] = make_float4(x, y, z, __int_as_float(i));
    }
}

// ---------------------------------------------------------------------------
// One level of inverse 3D Haar, channel-major fp32 output (C, 2D, 2D, 2D).
// ---------------------------------------------------------------------------
template <int D>
__global__ void idwt_small(const float* __restrict__ approx,
                           const float* __restrict__ det,
                           float* __restrict__ out) {
    const int vol = CH * D * D * D;
    int idx = blockIdx.x * blockDim.x + threadIdx.x;
    if (idx >= vol) return;
    int k = idx % D;
    int j = (idx / D) % D;
    int i = (idx / (D * D)) % D;
    int c = idx / (D * D * D);

    float a[8];
    a[0] = approx[idx];
#pragma unroll
    for (int s = 1; s < 8; s++) a[s] = det[(size_t)(s - 1) * vol + idx];

    const int R = 2 * D;
    size_t base = (((size_t)c * R + 2 * i) * R + 2 * j) * R + 2 * k;
#pragma unroll
    for (int p = 0; p < 2; p++)
#pragma unroll
        for (int q = 0; q < 2; q++) {
            float b0 = 0.f, b1 = 0.f;
#pragma unroll
            for (int u = 0; u < 2; u++)
#pragma unroll
                for (int v = 0; v < 2; v++) {
                    float sgn = ((u & p) ^ (v & q)) ? -1.f : 1.f;
                    b0 += sgn * a[u * 4 + v * 2 + 0];
                    b1 += sgn * a[u * 4 + v * 2 + 1];
                }
            float2 val = make_float2(INV_SQ8 * (b0 + b1), INV_SQ8 * (b0 - b1));
            *(float2*)(out + base + ((size_t)p * R + q) * R) = val;
        }
}

// ---------------------------------------------------------------------------
// Final IDWT level (64 -> 128) fused with transpose to channel-last fp32
// (z, y, x, 28). Block = 256 threads (28 ch x 8 k active), one (i,j) coarse
// pair x 8-k tile. Walks z DESCENDING so the low-z planes written last are
// still L2-resident when the (z-ascending) query starts.
// ---------------------------------------------------------------------------
__global__ void idwt_final(const float* __restrict__ approx,
                           const float* __restrict__ det,
                           float* __restrict__ out) {
    const int D = 64, R = 128;
    const int vol = CH * D * D * D;
    int bid = blockIdx.x;
    int ktile = bid & 7;
    int j = (bid >> 3) & 63;
    int i = 63 - (bid >> 9);        // reverse z order
    int k0 = ktile * 8;

    int tid = threadIdx.x;
    int c  = tid >> 3;   // 0..31, only 0..27 active
    int kl = tid & 7;    // 0..7

    __shared__ __align__(16) float sh[4][16 * CH];  // [pq][16 x-values x 28 ch]

    if (c < CH) {
        int idx = ((c * D + i) * D + j) * D + k0 + kl;
        float a[8];
        a[0] = __ldcs(approx + idx);
#pragma unroll
        for (int s = 1; s < 8; s++) a[s] = __ldcs(det + (size_t)(s - 1) * vol + idx);
#pragma unroll
        for (int p = 0; p < 2; p++)
#pragma unroll
            for (int q = 0; q < 2; q++) {
                float b0 = 0.f, b1 = 0.f;
#pragma unroll
                for (int u = 0; u < 2; u++)
#pragma unroll
                    for (int v = 0; v < 2; v++) {
                        float sgn = ((u & p) ^ (v & q)) ? -1.f : 1.f;
                        b0 += sgn * a[u * 4 + v * 2 + 0];
                        b1 += sgn * a[u * 4 + v * 2 + 1];
                    }
                sh[p * 2 + q][(2 * kl + 0) * CH + c] = INV_SQ8 * (b0 + b1);
                sh[p * 2 + q][(2 * kl + 1) * CH + c] = INV_SQ8 * (b0 - b1);
            }
    }
    __syncthreads();

    // 4 octants x 448 floats = 448 float4 total, contiguous bursts.
#pragma unroll
    for (int t = tid; t < 448; t += 256) {
        int pq = t / 112, r = t - pq * 112;
        int p = pq >> 1, q = pq & 1;
        size_t base = (((size_t)(2 * i + p) * R + (2 * j + q)) * R + 2 * k0) * CH;
        ((float4*)(out + base))[r] = ((const float4*)sh[pq])[r];
    }
}

// ---------------------------------------------------------------------------
// Trilinear query on z-sorted points: 4 points per warp, 7 active lanes per
// point, each lane handles 4 channels via float4. Each corner = 112B
// contiguous (4 sectors). Sorted order keeps a ~3.7 MB working set in L2.
// ---------------------------------------------------------------------------
__global__ void query_kernel(const float* __restrict__ vol,
                             float* __restrict__ out, int N) {
    int warp = (blockIdx.x * blockDim.x + threadIdx.x) >> 5;
    int lane = threadIdx.x & 31;
    int pt = warp * 4 + (lane >> 3);
    int l  = lane & 7;              // 0..7, active l<7 (channels 4l..4l+3)
    if (pt >= N) return;

    float4 s = g_sorted[pt];        // broadcast within 8-lane group
    int idx = __float_as_int(s.w);

    float px = (s.x / 1.5f + 1.0f) * 63.5f;
    float py = (s.y / 1.5f + 1.0f) * 63.5f;
    float pz = (s.z / 1.5f + 1.0f) * 63.5f;

    float flx = floorf(px), fly = floorf(py), flz = floorf(pz);
    float fx = px - flx, fy = py - fly, fz = pz - flz;
    int x0 = min(max((int)flx, 0), 126);
    int y0 = min(max((int)fly, 0), 126);
    int z0 = min(max((int)flz, 0), 126);

    if (l >= CH / 4) return;

    float wx1 = fx, wx0 = 1.f - fx;
    float wy1 = fy, wy0 = 1.f - fy;
    float wz1 = fz, wz0 = 1.f - fz;
    float w00 = wz0 * wy0, w01 = wz0 * wy1, w10 = wz1 * wy0, w11 = wz1 * wy1;

    const float4* base = (const float4*)vol +
                         (((size_t)z0 * 128 + y0) * 128 + x0) * (CH / 4) + l;
    const size_t DX = CH / 4;
    const size_t DY = (size_t)128 * (CH / 4);
    const size_t DZ = (size_t)128 * 128 * (CH / 4);

    float4 v000 = base[0];
    float4 v001 = base[DX];
    float4 v010 = base[DY];
    float4 v011 = base[DY + DX];
    float4 v100 = base[DZ];
    float4 v101 = base[DZ + DX];
    float4 v110 = base[DZ + DY];
    float4 v111 = base[DZ + DY + DX];

    float4 r;
    r.x = w00 * (wx0 * v000.x + wx1 * v001.x) + w01 * (wx0 * v010.x + wx1 * v011.x) +
          w10 * (wx0 * v100.x + wx1 * v101.x) + w11 * (wx0 * v110.x + wx1 * v111.x);
    r.y = w00 * (wx0 * v000.y + wx1 * v001.y) + w01 * (wx0 * v010.y + wx1 * v011.y) +
          w10 * (wx0 * v100.y + wx1 * v101.y) + w11 * (wx0 * v110.y + wx1 * v111.y);
    r.z = w00 * (wx0 * v000.z + wx1 * v001.z) + w01 * (wx0 * v010.z + wx1 * v011.z) +
          w10 * (wx0 * v100.z + wx1 * v101.z) + w11 * (wx0 * v110.z + wx1 * v111.z);
    r.w = w00 * (wx0 * v000.w + wx1 * v001.w) + w01 * (wx0 * v010.w + wx1 * v011.w) +
          w10 * (wx0 * v100.w + wx1 * v101.w) + w11 * (wx0 * v110.w + wx1 * v111.w);

    __stcs((float4*)(out + (size_t)idx * CH) + l, r);
}

extern "C" void kernel_launch(void* const* d_in, const int* in_sizes, int n_in,
                              void* d_out, int out_size) {
    const float* approx = (const float*)d_in[0];   // (28,16,16,16)
    const float* det0   = (const float*)d_in[1];   // (7,28,16,16,16)
    const float* det1   = (const float*)d_in[2];   // (7,28,32,32,32)
    const float* det2   = (const float*)d_in[3];   // (7,28,64,64,64)
    const float* xyz    = (const float*)d_in[4];   // (N,3)
    int N = in_sizes[4] / 3;

    float *vol1, *vol2, *volF;
    cudaGetSymbolAddress((void**)&vol1, g_vol1);
    cudaGetSymbolAddress((void**)&vol2, g_vol2);
    cudaGetSymbolAddress((void**)&volF, g_volF);

    // Sort chain (independent of IDWT; run first so scatter finishes early)
    zero_hist_kernel<<<1, 128>>>();
    hist_kernel<<<448, 256>>>(xyz, N);
    scan_kernel<<<1, 128>>>();
    scatter_kernel<<<448, 256>>>(xyz, N);

    {   // level 0: 16 -> 32
        int n = CH * 16 * 16 * 16;
        idwt_small<16><<<(n + 255) / 256, 256>>>(approx, det0, vol1);
    }
    {   // level 1: 32 -> 64
        int n = CH * 32 * 32 * 32;
        idwt_small<32><<<(n + 255) / 256, 256>>>(vol1, det1, vol2);
    }
    // level 2: 64 -> 128, fused transpose to fp32 (z,y,x,28), z descending
    idwt_final<<<64 * 64 * 8, 256>>>(vol2, det2, volF);

    // trilinear gather on sorted points: 32 points per 256-thread block
    query_kernel<<<(N + 31) / 32, 256>>>(volF, (float*)d_out, N);
}

// round 7
// speedup vs baseline: 1.6772x; 1.6772x over previous
#include <cuda_runtime.h>
#include <math.h>

#define CH 28
#define INV_SQ8 0.35355339059327373f
#define NMAX 1050000
#define SCHUNK 2048     // points per scatter block (256 thr x 8)

// Scratch (allocation-free contract: __device__ globals)
__device__ float  g_vol1[CH * 32 * 32 * 32];             //  3.5 MB fp32
__device__ float  g_vol2[CH * 64 * 64 * 64];             //   28 MB fp32
__device__ float  g_volF[(size_t)128 * 128 * 128 * CH];  //  235 MB fp32, (z,y,x,c) tight
__device__ float4 g_sorted[NMAX];                        // z-bucket-sorted (x,y,z,idx)
__device__ int    g_hist[128];
__device__ int    g_cursor[128];

// ---------------------------------------------------------------------------
// Sorting chain: bucket points by z0 (127 bins) via block-aggregated counting
// sort so the query walks the volume in z order (2-plane L2 working set).
// ---------------------------------------------------------------------------
__device__ __forceinline__ int zbin(float z) {
    float pz = (z / 1.5f + 1.0f) * 63.5f;
    return min(max((int)floorf(pz), 0), 126);
}

__global__ void zero_hist_kernel() {
    if (threadIdx.x < 128) g_hist[threadIdx.x] = 0;
}

__global__ void hist_kernel(const float* __restrict__ xyz, int N) {
    __shared__ int sh[128];
    if (threadIdx.x < 128) sh[threadIdx.x] = 0;
    __syncthreads();
    for (int i = blockIdx.x * blockDim.x + threadIdx.x; i < N;
         i += gridDim.x * blockDim.x)
        atomicAdd(&sh[zbin(xyz[3 * i + 2])], 1);
    __syncthreads();
    if (threadIdx.x < 128 && sh[threadIdx.x])
        atomicAdd(&g_hist[threadIdx.x], sh[threadIdx.x]);
}

__global__ void scan_kernel() {
    __shared__ int s[128];
    int t = threadIdx.x;            // blockDim = 128
    int v = g_hist[t];
    s[t] = v;
    __syncthreads();
#pragma unroll
    for (int off = 1; off < 128; off <<= 1) {
        int u = (t >= off) ? s[t - off] : 0;
        __syncthreads();
        s[t] += u;
        __syncthreads();
    }
    g_cursor[t] = s[t] - v;         // exclusive prefix
}

// Block-aggregated scatter: local ranks via smem atomics, ONE global
// atomicAdd per (block, bin) to reserve a contiguous output range.
__global__ void scatter_kernel(const float* __restrict__ xyz, int N) {
    __shared__ int sh_count[128];
    __shared__ int sh_base[128];

    int tid = threadIdx.x;
    if (tid < 128) sh_count[tid] = 0;
    __syncthreads();

    int start = blockIdx.x * SCHUNK;
    float px[8], py[8], pz[8];
    int code[8];                    // bin<<16 | local_rank

#pragma unroll
    for (int it = 0; it < 8; it++) {
        int i = start + it * 256 + tid;
        code[it] = -1;
        if (i < N) {
            px[it] = xyz[3 * i + 0];
            py[it] = xyz[3 * i + 1];
            pz[it] = xyz[3 * i + 2];
            int b = zbin(pz[it]);
            int r = atomicAdd(&sh_count[b], 1);
            code[it] = (b << 16) | r;
        }
    }
    __syncthreads();

    if (tid < 128) {
        int c = sh_count[tid];
        sh_base[tid] = c ? atomicAdd(&g_cursor[tid], c) : 0;
    }
    __syncthreads();

#pragma unroll
    for (int it = 0; it < 8; it++) {
        if (code[it] >= 0) {
            int b = code[it] >> 16, r = code[it] & 0xFFFF;
            int i = start + it * 256 + tid;
            g_sorted[sh_base[b] + r] =
                make_float4(px[it], py[it], pz[it], __int_as_float(i));
        }
    }
}

// ---------------------------------------------------------------------------
// One level of inverse 3D Haar, channel-major fp32 output (C, 2D, 2D, 2D).
// ---------------------------------------------------------------------------
template <int D>
__global__ void idwt_small(const float* __restrict__ approx,
                           const float* __restrict__ det,
                           float* __restrict__ out) {
    const int vol = CH * D * D * D;
    int idx = blockIdx.x * blockDim.x + threadIdx.x;
    if (idx >= vol) return;
    int k = idx % D;
    int j = (idx / D) % D;
    int i = (idx / (D * D)) % D;
    int c = idx / (D * D * D);

    float a[8];
    a[0] = approx[idx];
#pragma unroll
    for (int s = 1; s < 8; s++) a[s] = det[(size_t)(s - 1) * vol + idx];

    const int R = 2 * D;
    size_t base = (((size_t)c * R + 2 * i) * R + 2 * j) * R + 2 * k;
#pragma unroll
    for (int p = 0; p < 2; p++)
#pragma unroll
        for (int q = 0; q < 2; q++) {
            float b0 = 0.f, b1 = 0.f;
#pragma unroll
            for (int u = 0; u < 2; u++)
#pragma unroll
                for (int v = 0; v < 2; v++) {
                    float sgn = ((u & p) ^ (v & q)) ? -1.f : 1.f;
                    b0 += sgn * a[u * 4 + v * 2 + 0];
                    b1 += sgn * a[u * 4 + v * 2 + 1];
                }
            float2 val = make_float2(INV_SQ8 * (b0 + b1), INV_SQ8 * (b0 - b1));
            *(float2*)(out + base + ((size_t)p * R + q) * R) = val;
        }
}

// ---------------------------------------------------------------------------
// Final IDWT level (64 -> 128) fused with transpose to channel-last fp32
// (z, y, x, 28). Block = 256 threads (28 ch x 8 k active), one (i,j) coarse
// pair x 8-k tile. Walks z DESCENDING so the low-z planes written last are
// still L2-resident when the (z-ascending) query starts.
// ---------------------------------------------------------------------------
__global__ void idwt_final(const float* __restrict__ approx,
                           const float* __restrict__ det,
                           float* __restrict__ out) {
    const int D = 64, R = 128;
    const int vol = CH * D * D * D;
    int bid = blockIdx.x;
    int ktile = bid & 7;
    int j = (bid >> 3) & 63;
    int i = 63 - (bid >> 9);        // reverse z order
    int k0 = ktile * 8;

    int tid = threadIdx.x;
    int c  = tid >> 3;   // 0..31, only 0..27 active
    int kl = tid & 7;    // 0..7

    __shared__ __align__(16) float sh[4][16 * CH];  // [pq][16 x-values x 28 ch]

    if (c < CH) {
        int idx = ((c * D + i) * D + j) * D + k0 + kl;
        float a[8];
        a[0] = __ldcs(approx + idx);
#pragma unroll
        for (int s = 1; s < 8; s++) a[s] = __ldcs(det + (size_t)(s - 1) * vol + idx);
#pragma unroll
        for (int p = 0; p < 2; p++)
#pragma unroll
            for (int q = 0; q < 2; q++) {
                float b0 = 0.f, b1 = 0.f;
#pragma unroll
                for (int u = 0; u < 2; u++)
#pragma unroll
                    for (int v = 0; v < 2; v++) {
                        float sgn = ((u & p) ^ (v & q)) ? -1.f : 1.f;
                        b0 += sgn * a[u * 4 + v * 2 + 0];
                        b1 += sgn * a[u * 4 + v * 2 + 1];
                    }
                sh[p * 2 + q][(2 * kl + 0) * CH + c] = INV_SQ8 * (b0 + b1);
                sh[p * 2 + q][(2 * kl + 1) * CH + c] = INV_SQ8 * (b0 - b1);
            }
    }
    __syncthreads();

    // 4 octants x 448 floats = 448 float4 total, contiguous bursts.
#pragma unroll
    for (int t = tid; t < 448; t += 256) {
        int pq = t / 112, r = t - pq * 112;
        int p = pq >> 1, q = pq & 1;
        size_t base = (((size_t)(2 * i + p) * R + (2 * j + q)) * R + 2 * k0) * CH;
        ((float4*)(out + base))[r] = ((const float4*)sh[pq])[r];
    }
}

// ---------------------------------------------------------------------------
// Trilinear query on z-sorted points: 4 points per warp, 7 active lanes per
// point, each lane handles 4 channels via float4. Each corner = 112B
// contiguous (4 sectors). Sorted order keeps a ~3.7 MB working set in L2.
// ---------------------------------------------------------------------------
__global__ void query_kernel(const float* __restrict__ vol,
                             float* __restrict__ out, int N) {
    int warp = (blockIdx.x * blockDim.x + threadIdx.x) >> 5;
    int lane = threadIdx.x & 31;
    int pt = warp * 4 + (lane >> 3);
    int l  = lane & 7;              // 0..7, active l<7 (channels 4l..4l+3)
    if (pt >= N) return;

    float4 s = g_sorted[pt];        // broadcast within 8-lane group
    int idx = __float_as_int(s.w);

    float px = (s.x / 1.5f + 1.0f) * 63.5f;
    float py = (s.y / 1.5f + 1.0f) * 63.5f;
    float pz = (s.z / 1.5f + 1.0f) * 63.5f;

    float flx = floorf(px), fly = floorf(py), flz = floorf(pz);
    float fx = px - flx, fy = py - fly, fz = pz - flz;
    int x0 = min(max((int)flx, 0), 126);
    int y0 = min(max((int)fly, 0), 126);
    int z0 = min(max((int)flz, 0), 126);

    if (l >= CH / 4) return;

    float wx1 = fx, wx0 = 1.f - fx;
    float wy1 = fy, wy0 = 1.f - fy;
    float wz1 = fz, wz0 = 1.f - fz;
    float w00 = wz0 * wy0, w01 = wz0 * wy1, w10 = wz1 * wy0, w11 = wz1 * wy1;

    const float4* base = (const float4*)vol +
                         (((size_t)z0 * 128 + y0) * 128 + x0) * (CH / 4) + l;
    const size_t DX = CH / 4;
    const size_t DY = (size_t)128 * (CH / 4);
    const size_t DZ = (size_t)128 * 128 * (CH / 4);

    float4 v000 = base[0];
    float4 v001 = base[DX];
    float4 v010 = base[DY];
    float4 v011 = base[DY + DX];
    float4 v100 = base[DZ];
    float4 v101 = base[DZ + DX];
    float4 v110 = base[DZ + DY];
    float4 v111 = base[DZ + DY + DX];

    float4 r;
    r.x = w00 * (wx0 * v000.x + wx1 * v001.x) + w01 * (wx0 * v010.x + wx1 * v011.x) +
          w10 * (wx0 * v100.x + wx1 * v101.x) + w11 * (wx0 * v110.x + wx1 * v111.x);
    r.y = w00 * (wx0 * v000.y + wx1 * v001.y) + w01 * (wx0 * v010.y + wx1 * v011.y) +
          w10 * (wx0 * v100.y + wx1 * v101.y) + w11 * (wx0 * v110.y + wx1 * v111.y);
    r.z = w00 * (wx0 * v000.z + wx1 * v001.z) + w01 * (wx0 * v010.z + wx1 * v011.z) +
          w10 * (wx0 * v100.z + wx1 * v101.z) + w11 * (wx0 * v110.z + wx1 * v111.z);
    r.w = w00 * (wx0 * v000.w + wx1 * v001.w) + w01 * (wx0 * v010.w + wx1 * v011.w) +
          w10 * (wx0 * v100.w + wx1 * v111.w * 0.0f + wx1 * v101.w) + w11 * (wx0 * v110.w + wx1 * v111.w);

    __stcs((float4*)(out + (size_t)idx * CH) + l, r);
}

extern "C" void kernel_launch(void* const* d_in, const int* in_sizes, int n_in,
                              void* d_out, int out_size) {
    const float* approx = (const float*)d_in[0];   // (28,16,16,16)
    const float* det0   = (const float*)d_in[1];   // (7,28,16,16,16)
    const float* det1   = (const float*)d_in[2];   // (7,28,32,32,32)
    const float* det2   = (const float*)d_in[3];   // (7,28,64,64,64)
    const float* xyz    = (const float*)d_in[4];   // (N,3)
    int N = in_sizes[4] / 3;

    float *vol1, *vol2, *volF;
    cudaGetSymbolAddress((void**)&vol1, g_vol1);
    cudaGetSymbolAddress((void**)&vol2, g_vol2);
    cudaGetSymbolAddress((void**)&volF, g_volF);

    // Sort chain
    zero_hist_kernel<<<1, 128>>>();
    hist_kernel<<<448, 256>>>(xyz, N);
    scan_kernel<<<1, 128>>>();
    scatter_kernel<<<(N + SCHUNK - 1) / SCHUNK, 256>>>(xyz, N);

    {   // level 0: 16 -> 32
        int n = CH * 16 * 16 * 16;
        idwt_small<16><<<(n + 255) / 256, 256>>>(approx, det0, vol1);
    }
    {   // level 1: 32 -> 64
        int n = CH * 32 * 32 * 32;
        idwt_small<32><<<(n + 255) / 256, 256>>>(vol1, det1, vol2);
    }
    // level 2: 64 -> 128, fused transpose to fp32 (z,y,x,28), z descending
    idwt_final<<<64 * 64 * 8, 256>>>(vol2, det2, volF);

    // trilinear gather on sorted points: 32 points per 256-thread block
    query_kernel<<<(N + 31) / 32, 256>>>(volF, (float*)d_out, N);
}